// round 1
// baseline (speedup 1.0000x reference)
#include <cuda_runtime.h>
#include <stdint.h>

#define DIM_IN 16
#define CH 128
#define DIM_OUT 99
#define MAX_NNZ 1024

struct __align__(16) Term {
    unsigned int offx;   // byte offset into sx row block: mu1 * CH * 4
    unsigned int offy;   // byte offset into sy row block: mu2 * CH * 4
    float cg;
    float pad;
};

__device__ Term g_terms[MAX_NNZ];
__device__ int  g_rowptr[DIM_OUT + 1];

// ---------------------------------------------------------------------------
// Prep: deterministic (stable) counting sort of terms by mu3 into CSR layout.
// Runs once per launch (inside the graph). nnz ~ 350 so this is ~1-2 us.
// ---------------------------------------------------------------------------
__global__ void prep_kernel(const int* __restrict__ mu1,
                            const int* __restrict__ mu2,
                            const int* __restrict__ mu3,
                            const float* __restrict__ cg,
                            int nnz)
{
    __shared__ int sm3[MAX_NNZ];
    __shared__ int hist[DIM_OUT + 1];
    int t = threadIdx.x;

    if (t < DIM_OUT + 1) hist[t] = 0;
    __syncthreads();

    for (int k = t; k < nnz; k += blockDim.x) {
        int m = mu3[k];
        sm3[k] = m;
        atomicAdd(&hist[m], 1);
    }
    __syncthreads();

    if (t == 0) {
        int s = 0;
        for (int o = 0; o < DIM_OUT; o++) {
            int h = hist[o];
            g_rowptr[o] = s;
            hist[o] = s;       // becomes row start
            s += h;
        }
        g_rowptr[DIM_OUT] = s;
    }
    __syncthreads();

    // stable scatter: rank = #earlier terms with same mu3 (deterministic order)
    for (int k = t; k < nnz; k += blockDim.x) {
        int m = sm3[k];
        int rank = 0;
        for (int j = 0; j < k; j++) rank += (sm3[j] == m);
        int pos = hist[m] + rank;
        Term tm;
        tm.offx = (unsigned int)mu1[k] * (CH * 4u);
        tm.offy = (unsigned int)mu2[k] * (CH * 4u);
        tm.cg   = cg[k];
        tm.pad  = 0.0f;
        g_terms[pos] = tm;
    }
}

// ---------------------------------------------------------------------------
// Main: one block per edge. 64 threads, each owns 2 consecutive channels.
// x,y tiles + sorted terms staged in shared; each output element written once.
// ---------------------------------------------------------------------------
__global__ __launch_bounds__(64) void tp_kernel(const float* __restrict__ x,
                                                const float* __restrict__ y,
                                                float* __restrict__ out,
                                                int nnz)
{
    __shared__ __align__(16) float sx[DIM_IN * CH];
    __shared__ __align__(16) float sy[DIM_IN * CH];
    __shared__ Term sterms[MAX_NNZ];
    __shared__ int  srp[DIM_OUT + 1];

    const int t = threadIdx.x;          // 0..63
    const long long e = blockIdx.x;

    // cooperative load of x/y tiles (2048 floats each = 512 float4)
    const float4* x4 = (const float4*)(x + e * (DIM_IN * CH));
    const float4* y4 = (const float4*)(y + e * (DIM_IN * CH));
#pragma unroll
    for (int i = 0; i < (DIM_IN * CH / 4) / 64; i++) {
        ((float4*)sx)[t + i * 64] = x4[t + i * 64];
        ((float4*)sy)[t + i * 64] = y4[t + i * 64];
    }
    // terms + rowptr into shared
    const uint4* gt = (const uint4*)g_terms;
    for (int i = t; i < nnz; i += 64)
        ((uint4*)sterms)[i] = __ldg(&gt[i]);
    for (int i = t; i < DIM_OUT + 1; i += 64)
        srp[i] = g_rowptr[i];
    __syncthreads();

    const unsigned int cb = (unsigned int)t * 8u;   // this thread's channel-pair byte offset
    const char* sxb = (const char*)sx + cb;
    const char* syb = (const char*)sy + cb;
    float* oute = out + e * (DIM_OUT * CH) + t * 2;

#pragma unroll 1
    for (int o = 0; o < DIM_OUT; o++) {
        const int k0 = srp[o];
        const int k1 = srp[o + 1];
        float ax = 0.0f, ay = 0.0f;
        for (int k = k0; k < k1; ++k) {
            Term tm = sterms[k];
            float2 xv = *(const float2*)(sxb + tm.offx);
            float2 yv = *(const float2*)(syb + tm.offy);
            ax = fmaf(xv.x * yv.x, tm.cg, ax);
            ay = fmaf(xv.y * yv.y, tm.cg, ay);
        }
        *(float2*)(oute + o * CH) = make_float2(ax, ay);
    }
}

// ---------------------------------------------------------------------------
// Inputs (metadata order): x f32 [N,16,128], y f32 [N,16,128],
//                          mu1 i32 [nnz], mu2 i32 [nnz], mu3 i32 [nnz], cg f32 [nnz]
// Output: f32 [N,99,128]
// ---------------------------------------------------------------------------
extern "C" void kernel_launch(void* const* d_in, const int* in_sizes, int n_in,
                              void* d_out, int out_size)
{
    const float* x   = (const float*)d_in[0];
    const float* y   = (const float*)d_in[1];
    const int*   mu1 = (const int*)d_in[2];
    const int*   mu2 = (const int*)d_in[3];
    const int*   mu3 = (const int*)d_in[4];
    const float* cg  = (const float*)d_in[5];

    int nnz = in_sizes[2];
    if (nnz > MAX_NNZ) nnz = MAX_NNZ;   // capacity guard (actual nnz ~350)
    int N = in_sizes[0] / (DIM_IN * CH);

    prep_kernel<<<1, 1024>>>(mu1, mu2, mu3, cg, nnz);
    tp_kernel<<<N, 64>>>(x, y, (float*)d_out, nnz);
}

// round 2
// speedup vs baseline: 1.2846x; 1.2846x over previous
#include <cuda_runtime.h>
#include <stdint.h>

#define DIM_IN 16
#define CH 128
#define DIM_OUT 99
#define MAX_NNZ 512
#define EPB 2              // edges per block
#define THREADS (EPB * 64)

// Compact term: low u16 = byte offset for x row (mu1*512), high u16 = y row
// offset (mu2*512); .y = cg bits. 8 bytes -> LDS.64 per term.
__device__ uint2 g_terms[MAX_NNZ];
__device__ int   g_rowptr[DIM_OUT + 1];

// ---------------------------------------------------------------------------
// Prep: deterministic stable counting sort of terms by mu3 into CSR layout.
// ---------------------------------------------------------------------------
__global__ void prep_kernel(const int* __restrict__ mu1,
                            const int* __restrict__ mu2,
                            const int* __restrict__ mu3,
                            const float* __restrict__ cg,
                            int nnz)
{
    __shared__ int sm3[MAX_NNZ];
    __shared__ int hist[DIM_OUT + 1];
    int t = threadIdx.x;

    if (t < DIM_OUT + 1) hist[t] = 0;
    __syncthreads();

    for (int k = t; k < nnz; k += blockDim.x) {
        int m = mu3[k];
        sm3[k] = m;
        atomicAdd(&hist[m], 1);
    }
    __syncthreads();

    if (t == 0) {
        int s = 0;
        for (int o = 0; o < DIM_OUT; o++) {
            int h = hist[o];
            g_rowptr[o] = s;
            hist[o] = s;       // becomes running row start
            s += h;
        }
        g_rowptr[DIM_OUT] = s;
    }
    __syncthreads();

    // stable scatter: rank = #earlier terms with same mu3 (deterministic)
    for (int k = t; k < nnz; k += blockDim.x) {
        int m = sm3[k];
        int rank = 0;
        for (int j = 0; j < k; j++) rank += (sm3[j] == m);
        int pos = hist[m] + rank;
        unsigned int ox = (unsigned int)mu1[k] * (CH * 4u);   // <= 7680, fits u16
        unsigned int oy = (unsigned int)mu2[k] * (CH * 4u);
        uint2 tm;
        tm.x = ox | (oy << 16);
        tm.y = __float_as_uint(cg[k]);
        g_terms[pos] = tm;
    }
}

// ---------------------------------------------------------------------------
// Main: 2 edges per 128-thread block; 64 threads per edge, one channel pair
// (float2) per thread. Each output element written exactly once.
// ---------------------------------------------------------------------------
__global__ __launch_bounds__(THREADS, 6)
void tp_kernel(const float* __restrict__ x,
               const float* __restrict__ y,
               float* __restrict__ out,
               int nnz, int nEdges)
{
    __shared__ __align__(16) float sx[EPB * DIM_IN * CH];   // 16 KB
    __shared__ __align__(16) float sy[EPB * DIM_IN * CH];   // 16 KB
    __shared__ uint2 sterms[MAX_NNZ];                       //  4 KB
    __shared__ int   srp[DIM_OUT + 1];

    const int t    = threadIdx.x;        // 0..127
    const int sub  = t >> 6;             // edge within block
    const int lane = t & 63;             // channel pair within edge
    const long long ebase = (long long)blockIdx.x * EPB;

    // cooperative load of both edges' x/y tiles (contiguous in gmem):
    // EPB*2048 floats = 1024 float4 each for x and y; 8 float4 per thread.
    const float4* x4 = (const float4*)(x + ebase * (DIM_IN * CH));
    const float4* y4 = (const float4*)(y + ebase * (DIM_IN * CH));
#pragma unroll
    for (int i = 0; i < (EPB * DIM_IN * CH / 4) / THREADS; i++) {
        ((float4*)sx)[t + i * THREADS] = x4[t + i * THREADS];
        ((float4*)sy)[t + i * THREADS] = y4[t + i * THREADS];
    }
    for (int i = t; i < nnz; i += THREADS)
        sterms[i] = g_terms[i];
    for (int i = t; i < DIM_OUT + 1; i += THREADS)
        srp[i] = g_rowptr[i];
    __syncthreads();

    const char* sxb = (const char*)(sx + sub * (DIM_IN * CH)) + lane * 8;
    const char* syb = (const char*)(sy + sub * (DIM_IN * CH)) + lane * 8;
    float* oute = out + (ebase + sub) * (DIM_OUT * CH) + lane * 2;

#pragma unroll 1
    for (int o = 0; o < DIM_OUT; o++) {
        const int k0 = srp[o];
        const int k1 = srp[o + 1];
        float ax = 0.0f, ay = 0.0f;
#pragma unroll 2
        for (int k = k0; k < k1; ++k) {
            uint2 tm = sterms[k];
            unsigned int ox = tm.x & 0xFFFFu;
            unsigned int oy = tm.x >> 16;
            float cgv = __uint_as_float(tm.y);
            float2 xv = *(const float2*)(sxb + ox);
            float2 yv = *(const float2*)(syb + oy);
            ax = fmaf(xv.x * yv.x, cgv, ax);
            ay = fmaf(xv.y * yv.y, cgv, ay);
        }
        *(float2*)(oute + o * CH) = make_float2(ax, ay);
    }
}

// ---------------------------------------------------------------------------
// Inputs (metadata order): x f32 [N,16,128], y f32 [N,16,128],
//                          mu1 i32 [nnz], mu2 i32 [nnz], mu3 i32 [nnz], cg f32 [nnz]
// Output: f32 [N,99,128]
// ---------------------------------------------------------------------------
extern "C" void kernel_launch(void* const* d_in, const int* in_sizes, int n_in,
                              void* d_out, int out_size)
{
    const float* x   = (const float*)d_in[0];
    const float* y   = (const float*)d_in[1];
    const int*   mu1 = (const int*)d_in[2];
    const int*   mu2 = (const int*)d_in[3];
    const int*   mu3 = (const int*)d_in[4];
    const float* cg  = (const float*)d_in[5];

    int nnz = in_sizes[2];
    if (nnz > MAX_NNZ) nnz = MAX_NNZ;   // capacity guard (actual nnz ~350)
    int N = in_sizes[0] / (DIM_IN * CH);
    int nBlocks = (N + EPB - 1) / EPB;

    prep_kernel<<<1, 1024>>>(mu1, mu2, mu3, cg, nnz);
    tp_kernel<<<nBlocks, THREADS>>>(x, y, (float*)d_out, nnz, N);
}